// round 7
// baseline (speedup 1.0000x reference)
#include <cuda_runtime.h>
#include <math.h>

#define NN 50000
#define D 128
#define EMAX 800000
#define TILE 1024
#define NPART ((NN + TILE - 1) / TILE)   // 49

// ---- device scratch (no allocations allowed) ----
__device__ float g_ga[(size_t)NN * D];   // ping
__device__ float g_gb[(size_t)NN * D];   // pong
__device__ float g_dinv1[NN];
__device__ float g_dinv2[NN];
__device__ int   g_cnt1[NN];
__device__ int   g_cnt2[NN];
__device__ int   g_rowptr1[NN + 1];
__device__ int   g_rowptr2[NN + 1];
__device__ int   g_cursor1[NN];
__device__ int   g_cursor2[NN];
__device__ int   g_col1[EMAX];
__device__ int   g_col2[EMAX];
__device__ int   g_part1[NPART];
__device__ int   g_part2[NPART];

// ---- packed f32x2 helpers (sm_103a) ----
__device__ __forceinline__ unsigned long long pack2(float a) {
    unsigned long long r;
    asm("mov.b64 %0, {%1, %1};" : "=l"(r) : "f"(a));
    return r;
}
__device__ __forceinline__ void fma2(unsigned long long& d,
                                     unsigned long long a, unsigned long long b) {
    asm("fma.rn.f32x2 %0, %1, %2, %0;" : "+l"(d) : "l"(a), "l"(b));
}
__device__ __forceinline__ unsigned long long mul2(unsigned long long a,
                                                   unsigned long long b) {
    unsigned long long d;
    asm("mul.rn.f32x2 %0, %1, %2;" : "=l"(d) : "l"(a), "l"(b));
    return d;
}

// ---------------------------------------------------------------------------
__global__ void zero_both_kernel(int* __restrict__ c1, int* __restrict__ c2) {
    int i = blockIdx.x * blockDim.x + threadIdx.x;
    if (i < NN) c1[i] = 0;
    else if (i < 2 * NN) c2[i - NN] = 0;
}

__global__ void count_both_kernel(const int* __restrict__ ei1, int E1,
                                  const int* __restrict__ ei2, int E2,
                                  int* __restrict__ c1, int* __restrict__ c2) {
    int h1 = E1 >> 1, h2 = E2 >> 1;
    int i = blockIdx.x * blockDim.x + threadIdx.x;
    if (i < h1) {
        int2 d = reinterpret_cast<const int2*>(ei1 + E1)[i];
        atomicAdd(&c1[d.x], 1);
        atomicAdd(&c1[d.y], 1);
    } else if (i < h1 + h2) {
        int2 d = reinterpret_cast<const int2*>(ei2 + E2)[i - h1];
        atomicAdd(&c2[d.x], 1);
        atomicAdd(&c2[d.y], 1);
    } else {
        int k = i - h1 - h2;
        if (k == 0 && (E1 & 1)) atomicAdd(&c1[ei1[E1 + E1 - 1]], 1);
        if (k == 1 && (E2 & 1)) atomicAdd(&c2[ei2[E2 + E2 - 1]], 1);
    }
}

__global__ __launch_bounds__(256) void partial_dinv_kernel(
    const int* __restrict__ c1, float* __restrict__ d1, int* __restrict__ p1,
    const int* __restrict__ c2, float* __restrict__ d2, int* __restrict__ p2)
{
    int set = (blockIdx.x >= NPART) ? 1 : 0;
    int b = blockIdx.x - set * NPART;
    const int* c = set ? c2 : c1;
    float* dv    = set ? d2 : d1;
    int* part    = set ? p2 : p1;

    __shared__ int wsum[8];
    int tid = threadIdx.x;
    int base = b * TILE + tid * 4;
    int s = 0;
    #pragma unroll
    for (int k = 0; k < 4; k++) {
        int i = base + k;
        if (i < NN) {
            int v = c[i];
            s += v;
            dv[i] = rsqrtf((float)v + 1.0f);
        }
    }
    #pragma unroll
    for (int off = 16; off > 0; off >>= 1)
        s += __shfl_down_sync(0xFFFFFFFFu, s, off);
    if ((tid & 31) == 0) wsum[tid >> 5] = s;
    __syncthreads();
    if (tid < 8) {
        int t = wsum[tid];
        #pragma unroll
        for (int off = 4; off > 0; off >>= 1)
            t += __shfl_down_sync(0xFFu, t, off);
        if (tid == 0) part[b] = t;
    }
}

__global__ __launch_bounds__(64) void scan_partials_kernel(
    int* __restrict__ p1, int* __restrict__ rp1,
    int* __restrict__ p2, int* __restrict__ rp2)
{
    int* part = blockIdx.x ? p2 : p1;
    int* rp   = blockIdx.x ? rp2 : rp1;
    __shared__ int w0_total;
    int tid = threadIdx.x;
    int lane = tid & 31;
    int wid = tid >> 5;
    int v = (tid < NPART) ? part[tid] : 0;
    int incl = v;
    #pragma unroll
    for (int off = 1; off < 32; off <<= 1) {
        int t = __shfl_up_sync(0xFFFFFFFFu, incl, off);
        if (lane >= off) incl += t;
    }
    if (tid == 31) w0_total = incl;
    __syncthreads();
    if (wid == 1) incl += w0_total;
    if (tid < NPART) part[tid] = incl - v;
    if (tid == NPART - 1) rp[NN] = incl;
}

__global__ __launch_bounds__(1024) void scan_tiles_kernel(
    const int* __restrict__ c1, int* __restrict__ rp1, int* __restrict__ cur1,
    const int* __restrict__ p1,
    const int* __restrict__ c2, int* __restrict__ rp2, int* __restrict__ cur2,
    const int* __restrict__ p2)
{
    int set = (blockIdx.x >= NPART) ? 1 : 0;
    int b = blockIdx.x - set * NPART;
    const int* cnt  = set ? c2 : c1;
    int* rp         = set ? rp2 : rp1;
    int* cur        = set ? cur2 : cur1;
    const int* part = set ? p2 : p1;

    __shared__ int warp_sums[32];
    int tid = threadIdx.x;
    int lane = tid & 31;
    int wid = tid >> 5;
    int i = b * TILE + tid;
    int v = (i < NN) ? cnt[i] : 0;
    int incl = v;
    #pragma unroll
    for (int off = 1; off < 32; off <<= 1) {
        int t = __shfl_up_sync(0xFFFFFFFFu, incl, off);
        if (lane >= off) incl += t;
    }
    if (lane == 31) warp_sums[wid] = incl;
    __syncthreads();
    if (wid == 0) {
        int s = warp_sums[lane];
        #pragma unroll
        for (int off = 1; off < 32; off <<= 1) {
            int t = __shfl_up_sync(0xFFFFFFFFu, s, off);
            if (lane >= off) s += t;
        }
        warp_sums[lane] = s;
    }
    __syncthreads();
    int woff = (wid > 0) ? warp_sums[wid - 1] : 0;
    int excl = incl - v + woff + part[b];
    if (i < NN) { rp[i] = excl; cur[i] = excl; }
}

__global__ void fill_both_kernel(const int* __restrict__ ei1, int E1,
                                 int* __restrict__ cur1, int* __restrict__ col1,
                                 const int* __restrict__ ei2, int E2,
                                 int* __restrict__ cur2, int* __restrict__ col2)
{
    int h1 = E1 >> 1, h2 = E2 >> 1;
    int i = blockIdx.x * blockDim.x + threadIdx.x;
    if (i < h1) {
        int2 s = reinterpret_cast<const int2*>(ei1)[i];
        int2 d = reinterpret_cast<const int2*>(ei1 + E1)[i];
        col1[atomicAdd(&cur1[d.x], 1)] = s.x;
        col1[atomicAdd(&cur1[d.y], 1)] = s.y;
    } else if (i < h1 + h2) {
        int2 s = reinterpret_cast<const int2*>(ei2)[i - h1];
        int2 d = reinterpret_cast<const int2*>(ei2 + E2)[i - h1];
        col2[atomicAdd(&cur2[d.x], 1)] = s.x;
        col2[atomicAdd(&cur2[d.y], 1)] = s.y;
    } else {
        int k = i - h1 - h2;
        if (k == 0 && (E1 & 1))
            col1[atomicAdd(&cur1[ei1[E1 + E1 - 1]], 1)] = ei1[E1 - 1];
        if (k == 1 && (E2 & 1))
            col2[atomicAdd(&cur2[ei2[E2 + E2 - 1]], 1)] = ei2[E2 - 1];
    }
}

// ---------------------------------------------------------------------------
// Shared GEMM phase: acc from As (smem) x W (gmem, staged 16-k chunks), then
// scale by dinv_next[row] and write g_out. Known-good round-4 structure.
__device__ __forceinline__ void gemm_phase(
    const float (*As)[132], float (*Ws)[128],
    const float* __restrict__ W, const float* __restrict__ dinv_next,
    float* __restrict__ g_out, int row_base, int tid)
{
    const int tx = tid & 15;
    const int ty = tid >> 4;
    const int col0 = tx * 8;
    const int row0 = ty * 8;

    unsigned long long acc2[8][4];
    #pragma unroll
    for (int r = 0; r < 8; r++)
        #pragma unroll
        for (int c = 0; c < 4; c++) acc2[r][c] = 0ull;

    for (int kc = 0; kc < D; kc += 16) {
        __syncthreads();
        #pragma unroll
        for (int i = tid; i < 512; i += 128) {
            int kk = i >> 5, c4 = i & 31;
            reinterpret_cast<float4*>(&Ws[kk][c4 * 4])[0] =
                reinterpret_cast<const float4*>(W)[(kc + kk) * 32 + c4];
        }
        __syncthreads();

        #pragma unroll
        for (int kk4 = 0; kk4 < 16; kk4 += 4) {
            float4 av[8];
            #pragma unroll
            for (int r = 0; r < 8; r++)
                av[r] = *reinterpret_cast<const float4*>(&As[row0 + r][kc + kk4]);

            #pragma unroll
            for (int j = 0; j < 4; j++) {
                union { float4 f; unsigned long long u[2]; } w0, w1;
                w0.f = *reinterpret_cast<const float4*>(&Ws[kk4 + j][col0]);
                w1.f = *reinterpret_cast<const float4*>(&Ws[kk4 + j][col0 + 4]);
                unsigned long long wv[4] = { w0.u[0], w0.u[1], w1.u[0], w1.u[1] };
                const float* avf = reinterpret_cast<const float*>(av);
                #pragma unroll
                for (int r = 0; r < 8; r++) {
                    unsigned long long aa = pack2(avf[r * 4 + j]);
                    fma2(acc2[r][0], aa, wv[0]);
                    fma2(acc2[r][1], aa, wv[1]);
                    fma2(acc2[r][2], aa, wv[2]);
                    fma2(acc2[r][3], aa, wv[3]);
                }
            }
        }
    }

    #pragma unroll
    for (int r = 0; r < 8; r++) {
        int row = row_base + row0 + r;
        if (row >= NN) continue;
        unsigned long long dd = pack2(dinv_next[row]);
        union { float4 f; unsigned long long u[2]; } o0, o1;
        o0.u[0] = mul2(acc2[r][0], dd);
        o0.u[1] = mul2(acc2[r][1], dd);
        o1.u[0] = mul2(acc2[r][2], dd);
        o1.u[1] = mul2(acc2[r][3], dd);
        long base = (long)row * 32 + (col0 >> 2);
        reinterpret_cast<float4*>(g_out)[base]     = o0.f;
        reinterpret_cast<float4*>(g_out)[base + 1] = o1.f;
    }
}

// Per-node gather into a float4 (one lane = 4 feature cols), with ELU finalize.
__device__ __forceinline__ float4 gather_node_elu(
    const float4* __restrict__ g, const int* __restrict__ row_ptr,
    const int* __restrict__ col, const float* __restrict__ dinv,
    float4 bb, int node, int lane)
{
    float4 a0 = g[(long)node * 32 + lane];
    float4 a1 = make_float4(0.f, 0.f, 0.f, 0.f);
    float4 a2 = make_float4(0.f, 0.f, 0.f, 0.f);
    float4 a3 = make_float4(0.f, 0.f, 0.f, 0.f);

    int jb = __ldg(&row_ptr[node]);
    int je = __ldg(&row_ptr[node + 1]);
    int j = jb;
    for (; j + 3 < je; j += 4) {
        int s0 = __ldg(&col[j]);
        int s1 = __ldg(&col[j + 1]);
        int s2 = __ldg(&col[j + 2]);
        int s3 = __ldg(&col[j + 3]);
        float4 v0 = g[(long)s0 * 32 + lane];
        float4 v1 = g[(long)s1 * 32 + lane];
        float4 v2 = g[(long)s2 * 32 + lane];
        float4 v3 = g[(long)s3 * 32 + lane];
        a0.x += v0.x; a0.y += v0.y; a0.z += v0.z; a0.w += v0.w;
        a1.x += v1.x; a1.y += v1.y; a1.z += v1.z; a1.w += v1.w;
        a2.x += v2.x; a2.y += v2.y; a2.z += v2.z; a2.w += v2.w;
        a3.x += v3.x; a3.y += v3.y; a3.z += v3.z; a3.w += v3.w;
    }
    for (; j < je; j++) {
        int s = __ldg(&col[j]);
        float4 v = g[(long)s * 32 + lane];
        a0.x += v.x; a0.y += v.y; a0.z += v.z; a0.w += v.w;
    }
    a0.x += a1.x + a2.x + a3.x;
    a0.y += a1.y + a2.y + a3.y;
    a0.z += a1.z + a2.z + a3.z;
    a0.w += a1.w + a2.w + a3.w;

    float dv = dinv[node];
    float o[4] = { fmaf(a0.x, dv, bb.x), fmaf(a0.y, dv, bb.y),
                   fmaf(a0.z, dv, bb.z), fmaf(a0.w, dv, bb.w) };
    #pragma unroll
    for (int k = 0; k < 4; k++) o[k] = (o[k] > 0.0f) ? o[k] : expm1f(o[k]);
    return make_float4(o[0], o[1], o[2], o[3]);
}

// ---------------------------------------------------------------------------
// Standalone GEMM (layer 1): g = (A @ W) * dinv[row].
__global__ __launch_bounds__(128) void gemm_scale_kernel(
    const float* __restrict__ A, const float* __restrict__ W,
    const float* __restrict__ dinv, float* __restrict__ g)
{
    __shared__ float As[64][132];
    __shared__ float Ws[16][128];

    const int tid = threadIdx.x;
    const int row_base = blockIdx.x * 64;

    #pragma unroll
    for (int i = tid; i < 64 * 32; i += 128) {
        int r = i >> 5, c4 = i & 31;
        float4 v = make_float4(0.f, 0.f, 0.f, 0.f);
        if (row_base + r < NN)
            v = reinterpret_cast<const float4*>(A)[(long)(row_base + r) * 32 + c4];
        *reinterpret_cast<float4*>(&As[r][c4 * 4]) = v;
    }
    gemm_phase(As, Ws, W, dinv, g, row_base, tid);
}

// ---------------------------------------------------------------------------
// Fused: gather layer i (ELU) into smem A-tile, then GEMM layer i+1.
// Optionally writes the activation tile to z_out (layer 2 -> d_out).
__global__ __launch_bounds__(128) void fused_gather_gemm_kernel(
    const float4* __restrict__ g_in, const int* __restrict__ row_ptr,
    const int* __restrict__ col, const float* __restrict__ dinv_g,
    const float4* __restrict__ bias,
    const float* __restrict__ W_next, const float* __restrict__ dinv_next,
    float* __restrict__ g_out, float4* __restrict__ z_out)
{
    __shared__ float As[64][132];
    __shared__ float Ws[16][128];

    const int tid = threadIdx.x;
    const int lane = tid & 31;
    const int w = tid >> 5;
    const int row_base = blockIdx.x * 64;

    float4 bb = bias[lane];

    // Phase 1: gather 16 nodes per warp into the A-tile.
    #pragma unroll 1
    for (int i = 0; i < 16; i++) {
        int r = w * 16 + i;
        int node = row_base + r;
        float4 val = make_float4(0.f, 0.f, 0.f, 0.f);
        if (node < NN) {
            val = gather_node_elu(g_in, row_ptr, col, dinv_g, bb, node, lane);
            if (z_out) z_out[(long)node * 32 + lane] = val;
        }
        *reinterpret_cast<float4*>(&As[r][lane * 4]) = val;
    }
    // (first __syncthreads inside gemm_phase orders the A-tile)

    // Phase 2: GEMM for next layer.
    gemm_phase(As, Ws, W_next, dinv_next, g_out, row_base, tid);
}

// ---------------------------------------------------------------------------
// Standalone final gather (layer 4, ReLU).
__global__ __launch_bounds__(256) void gather_finalize_relu_kernel(
    const float4* __restrict__ g, const int* __restrict__ row_ptr,
    const int* __restrict__ col, const float* __restrict__ dinv,
    const float4* __restrict__ b, float4* __restrict__ out)
{
    int warp = (blockIdx.x * blockDim.x + threadIdx.x) >> 5;
    int lane = threadIdx.x & 31;
    if (warp >= NN) return;

    float4 a0 = g[(long)warp * 32 + lane];
    float4 a1 = make_float4(0.f, 0.f, 0.f, 0.f);
    float4 a2 = make_float4(0.f, 0.f, 0.f, 0.f);
    float4 a3 = make_float4(0.f, 0.f, 0.f, 0.f);

    int jb = __ldg(&row_ptr[warp]);
    int je = __ldg(&row_ptr[warp + 1]);
    int j = jb;
    for (; j + 3 < je; j += 4) {
        int s0 = __ldg(&col[j]);
        int s1 = __ldg(&col[j + 1]);
        int s2 = __ldg(&col[j + 2]);
        int s3 = __ldg(&col[j + 3]);
        float4 v0 = g[(long)s0 * 32 + lane];
        float4 v1 = g[(long)s1 * 32 + lane];
        float4 v2 = g[(long)s2 * 32 + lane];
        float4 v3 = g[(long)s3 * 32 + lane];
        a0.x += v0.x; a0.y += v0.y; a0.z += v0.z; a0.w += v0.w;
        a1.x += v1.x; a1.y += v1.y; a1.z += v1.z; a1.w += v1.w;
        a2.x += v2.x; a2.y += v2.y; a2.z += v2.z; a2.w += v2.w;
        a3.x += v3.x; a3.y += v3.y; a3.z += v3.z; a3.w += v3.w;
    }
    for (; j < je; j++) {
        int s = __ldg(&col[j]);
        float4 v = g[(long)s * 32 + lane];
        a0.x += v.x; a0.y += v.y; a0.z += v.z; a0.w += v.w;
    }
    a0.x += a1.x + a2.x + a3.x;
    a0.y += a1.y + a2.y + a3.y;
    a0.z += a1.z + a2.z + a3.z;
    a0.w += a1.w + a2.w + a3.w;

    float dv = dinv[warp];
    float4 bb = b[lane];
    float4 o = make_float4(fmaxf(fmaf(a0.x, dv, bb.x), 0.0f),
                           fmaxf(fmaf(a0.y, dv, bb.y), 0.0f),
                           fmaxf(fmaf(a0.z, dv, bb.z), 0.0f),
                           fmaxf(fmaf(a0.w, dv, bb.w), 0.0f));
    out[(long)warp * 32 + lane] = o;
}

// ---------------------------------------------------------------------------
extern "C" void kernel_launch(void* const* d_in, const int* in_sizes, int n_in,
                              void* d_out, int out_size)
{
    const float* x  = (const float*)d_in[0];
    const float* W1 = (const float*)d_in[1]; const float* b1 = (const float*)d_in[2];
    const float* W2 = (const float*)d_in[3]; const float* b2 = (const float*)d_in[4];
    const float* W3 = (const float*)d_in[5]; const float* b3 = (const float*)d_in[6];
    const float* W4 = (const float*)d_in[7]; const float* b4 = (const float*)d_in[8];
    const int* ei1 = (const int*)d_in[9];
    const int* ei2 = (const int*)d_in[10];
    const int E1 = in_sizes[9] / 2;
    const int E2 = in_sizes[10] / 2;

    float *ga, *gb, *dinv1, *dinv2;
    int *cnt1, *cnt2, *rp1, *rp2, *cur1, *cur2, *col1, *col2, *p1, *p2;
    cudaGetSymbolAddress((void**)&ga,   g_ga);
    cudaGetSymbolAddress((void**)&gb,   g_gb);
    cudaGetSymbolAddress((void**)&dinv1, g_dinv1);
    cudaGetSymbolAddress((void**)&dinv2, g_dinv2);
    cudaGetSymbolAddress((void**)&cnt1, g_cnt1);
    cudaGetSymbolAddress((void**)&cnt2, g_cnt2);
    cudaGetSymbolAddress((void**)&rp1,  g_rowptr1);
    cudaGetSymbolAddress((void**)&rp2,  g_rowptr2);
    cudaGetSymbolAddress((void**)&cur1, g_cursor1);
    cudaGetSymbolAddress((void**)&cur2, g_cursor2);
    cudaGetSymbolAddress((void**)&col1, g_col1);
    cudaGetSymbolAddress((void**)&col2, g_col2);
    cudaGetSymbolAddress((void**)&p1,   g_part1);
    cudaGetSymbolAddress((void**)&p2,   g_part2);

    float* out_z = (float*)d_out;
    float* out_x = (float*)d_out + (long)NN * D;

    // ---- CSR build ----
    int nedge2 = (E1 >> 1) + (E2 >> 1) + 2;
    zero_both_kernel<<<(2 * NN + 255) / 256, 256>>>(cnt1, cnt2);
    count_both_kernel<<<(nedge2 + 255) / 256, 256>>>(ei1, E1, ei2, E2, cnt1, cnt2);
    partial_dinv_kernel<<<2 * NPART, 256>>>(cnt1, dinv1, p1, cnt2, dinv2, p2);
    scan_partials_kernel<<<2, 64>>>(p1, rp1, p2, rp2);
    scan_tiles_kernel<<<2 * NPART, 1024>>>(cnt1, rp1, cur1, p1, cnt2, rp2, cur2, p2);
    fill_both_kernel<<<(nedge2 + 255) / 256, 256>>>(ei1, E1, cur1, col1,
                                                    ei2, E2, cur2, col2);

    const int gemm_blocks = (NN + 63) / 64;
    const int gat_blocks  = (NN * 32 + 255) / 256;

    // Layer 1 GEMM: ga = (x @ W1) * dinv1
    gemm_scale_kernel<<<gemm_blocks, 128>>>(x, W1, dinv1, ga);
    // F1: gather(ei1, dinv1, b1, elu) -> GEMM W2 -> gb = (act1 @ W2) * dinv2
    fused_gather_gemm_kernel<<<gemm_blocks, 128>>>(
        (const float4*)ga, rp1, col1, dinv1, (const float4*)b1,
        W2, dinv2, gb, nullptr);
    // F2: gather(ei2, dinv2, b2, elu) -> z to d_out; GEMM W3 -> ga
    fused_gather_gemm_kernel<<<gemm_blocks, 128>>>(
        (const float4*)gb, rp2, col2, dinv2, (const float4*)b2,
        W3, dinv1, ga, (float4*)out_z);
    // F3: gather(ei1, dinv1, b3, elu) -> GEMM W4 -> gb
    fused_gather_gemm_kernel<<<gemm_blocks, 128>>>(
        (const float4*)ga, rp1, col1, dinv1, (const float4*)b3,
        W4, dinv2, gb, nullptr);
    // Final gather (ei2, dinv2, b4, relu) -> out_x
    gather_finalize_relu_kernel<<<gat_blocks, 256>>>(
        (const float4*)gb, rp2, col2, dinv2, (const float4*)b4,
        (float4*)out_x);
}

// round 8
// speedup vs baseline: 1.2492x; 1.2492x over previous
#include <cuda_runtime.h>
#include <math.h>

#define NN 50000
#define D 128
#define EMAX 800000
#define TILE 1024
#define NPART ((NN + TILE - 1) / TILE)   // 49

// ---- device scratch (no allocations allowed; zero-initialized at load) ----
__device__ float g_ga[(size_t)NN * D];   // g buffer
__device__ float g_gb[(size_t)NN * D];   // act buffer
__device__ float g_dinv1[NN];
__device__ float g_dinv2[NN];
__device__ int   g_cnt1[NN];             // kept zeroed by scan_tiles_kernel
__device__ int   g_cnt2[NN];
__device__ int   g_rowptr1[NN + 1];
__device__ int   g_rowptr2[NN + 1];
__device__ int   g_cursor1[NN];
__device__ int   g_cursor2[NN];
__device__ int   g_col1[EMAX];
__device__ int   g_col2[EMAX];
__device__ int   g_part1[NPART];
__device__ int   g_part2[NPART];

// ---- packed f32x2 helpers (sm_103a) ----
__device__ __forceinline__ unsigned long long pack2(float a) {
    unsigned long long r;
    asm("mov.b64 %0, {%1, %1};" : "=l"(r) : "f"(a));
    return r;
}
__device__ __forceinline__ void fma2(unsigned long long& d,
                                     unsigned long long a, unsigned long long b) {
    asm("fma.rn.f32x2 %0, %1, %2, %0;" : "+l"(d) : "l"(a), "l"(b));
}
__device__ __forceinline__ unsigned long long mul2(unsigned long long a,
                                                   unsigned long long b) {
    unsigned long long d;
    asm("mul.rn.f32x2 %0, %1, %2;" : "=l"(d) : "l"(a), "l"(b));
    return d;
}

// ---------------------------------------------------------------------------
// Count in-degrees, 2 edges per thread (counts arrive zeroed — see scan_tiles).
__global__ void count_both_kernel(const int* __restrict__ ei1, int E1,
                                  const int* __restrict__ ei2, int E2,
                                  int* __restrict__ c1, int* __restrict__ c2) {
    int h1 = E1 >> 1, h2 = E2 >> 1;
    int i = blockIdx.x * blockDim.x + threadIdx.x;
    if (i < h1) {
        int2 d = reinterpret_cast<const int2*>(ei1 + E1)[i];
        atomicAdd(&c1[d.x], 1);
        atomicAdd(&c1[d.y], 1);
    } else if (i < h1 + h2) {
        int2 d = reinterpret_cast<const int2*>(ei2 + E2)[i - h1];
        atomicAdd(&c2[d.x], 1);
        atomicAdd(&c2[d.y], 1);
    } else {
        int k = i - h1 - h2;
        if (k == 0 && (E1 & 1)) atomicAdd(&c1[ei1[E1 + E1 - 1]], 1);
        if (k == 1 && (E2 & 1)) atomicAdd(&c2[ei2[E2 + E2 - 1]], 1);
    }
}

__global__ __launch_bounds__(256) void partial_dinv_kernel(
    const int* __restrict__ c1, float* __restrict__ d1, int* __restrict__ p1,
    const int* __restrict__ c2, float* __restrict__ d2, int* __restrict__ p2)
{
    int set = (blockIdx.x >= NPART) ? 1 : 0;
    int b = blockIdx.x - set * NPART;
    const int* c = set ? c2 : c1;
    float* dv    = set ? d2 : d1;
    int* part    = set ? p2 : p1;

    __shared__ int wsum[8];
    int tid = threadIdx.x;
    int base = b * TILE + tid * 4;
    int s = 0;
    #pragma unroll
    for (int k = 0; k < 4; k++) {
        int i = base + k;
        if (i < NN) {
            int v = c[i];
            s += v;
            dv[i] = rsqrtf((float)v + 1.0f);
        }
    }
    #pragma unroll
    for (int off = 16; off > 0; off >>= 1)
        s += __shfl_down_sync(0xFFFFFFFFu, s, off);
    if ((tid & 31) == 0) wsum[tid >> 5] = s;
    __syncthreads();
    if (tid < 8) {
        int t = wsum[tid];
        #pragma unroll
        for (int off = 4; off > 0; off >>= 1)
            t += __shfl_down_sync(0xFFu, t, off);
        if (tid == 0) part[b] = t;
    }
}

__global__ __launch_bounds__(64) void scan_partials_kernel(
    int* __restrict__ p1, int* __restrict__ rp1,
    int* __restrict__ p2, int* __restrict__ rp2)
{
    int* part = blockIdx.x ? p2 : p1;
    int* rp   = blockIdx.x ? rp2 : rp1;
    __shared__ int w0_total;
    int tid = threadIdx.x;
    int lane = tid & 31;
    int wid = tid >> 5;
    int v = (tid < NPART) ? part[tid] : 0;
    int incl = v;
    #pragma unroll
    for (int off = 1; off < 32; off <<= 1) {
        int t = __shfl_up_sync(0xFFFFFFFFu, incl, off);
        if (lane >= off) incl += t;
    }
    if (tid == 31) w0_total = incl;
    __syncthreads();
    if (wid == 1) incl += w0_total;
    if (tid < NPART) part[tid] = incl - v;
    if (tid == NPART - 1) rp[NN] = incl;
}

// Per-tile scan + offset; ALSO zeroes cnt after reading (maintains the
// counts-are-zero invariant for the next graph replay).
__global__ __launch_bounds__(1024) void scan_tiles_kernel(
    int* __restrict__ c1, int* __restrict__ rp1, int* __restrict__ cur1,
    const int* __restrict__ p1,
    int* __restrict__ c2, int* __restrict__ rp2, int* __restrict__ cur2,
    const int* __restrict__ p2)
{
    int set = (blockIdx.x >= NPART) ? 1 : 0;
    int b = blockIdx.x - set * NPART;
    int* cnt        = set ? c2 : c1;
    int* rp         = set ? rp2 : rp1;
    int* cur        = set ? cur2 : cur1;
    const int* part = set ? p2 : p1;

    __shared__ int warp_sums[32];
    int tid = threadIdx.x;
    int lane = tid & 31;
    int wid = tid >> 5;
    int i = b * TILE + tid;
    int v = (i < NN) ? cnt[i] : 0;
    int incl = v;
    #pragma unroll
    for (int off = 1; off < 32; off <<= 1) {
        int t = __shfl_up_sync(0xFFFFFFFFu, incl, off);
        if (lane >= off) incl += t;
    }
    if (lane == 31) warp_sums[wid] = incl;
    __syncthreads();
    if (wid == 0) {
        int s = warp_sums[lane];
        #pragma unroll
        for (int off = 1; off < 32; off <<= 1) {
            int t = __shfl_up_sync(0xFFFFFFFFu, s, off);
            if (lane >= off) s += t;
        }
        warp_sums[lane] = s;
    }
    __syncthreads();
    int woff = (wid > 0) ? warp_sums[wid - 1] : 0;
    int excl = incl - v + woff + part[b];
    if (i < NN) { rp[i] = excl; cur[i] = excl; cnt[i] = 0; }
}

// ---------------------------------------------------------------------------
// Shared GEMM phase: acc from As (smem) x W (gmem, staged 16-k chunks), then
// scale by dinv_next[row] and write g_out. Known-good round-4/5 structure.
__device__ __forceinline__ void gemm_phase(
    const float (*As)[132], float (*Ws)[128],
    const float* __restrict__ W, const float* __restrict__ dinv_next,
    float* __restrict__ g_out, int row_base, int tid)
{
    const int tx = tid & 15;
    const int ty = tid >> 4;
    const int col0 = tx * 8;
    const int row0 = ty * 8;

    unsigned long long acc2[8][4];
    #pragma unroll
    for (int r = 0; r < 8; r++)
        #pragma unroll
        for (int c = 0; c < 4; c++) acc2[r][c] = 0ull;

    for (int kc = 0; kc < D; kc += 16) {
        __syncthreads();
        #pragma unroll
        for (int i = tid; i < 512; i += 128) {
            int kk = i >> 5, c4 = i & 31;
            reinterpret_cast<float4*>(&Ws[kk][c4 * 4])[0] =
                reinterpret_cast<const float4*>(W)[(kc + kk) * 32 + c4];
        }
        __syncthreads();

        #pragma unroll
        for (int kk4 = 0; kk4 < 16; kk4 += 4) {
            float4 av[8];
            #pragma unroll
            for (int r = 0; r < 8; r++)
                av[r] = *reinterpret_cast<const float4*>(&As[row0 + r][kc + kk4]);

            #pragma unroll
            for (int j = 0; j < 4; j++) {
                union { float4 f; unsigned long long u[2]; } w0, w1;
                w0.f = *reinterpret_cast<const float4*>(&Ws[kk4 + j][col0]);
                w1.f = *reinterpret_cast<const float4*>(&Ws[kk4 + j][col0 + 4]);
                unsigned long long wv[4] = { w0.u[0], w0.u[1], w1.u[0], w1.u[1] };
                const float* avf = reinterpret_cast<const float*>(av);
                #pragma unroll
                for (int r = 0; r < 8; r++) {
                    unsigned long long aa = pack2(avf[r * 4 + j]);
                    fma2(acc2[r][0], aa, wv[0]);
                    fma2(acc2[r][1], aa, wv[1]);
                    fma2(acc2[r][2], aa, wv[2]);
                    fma2(acc2[r][3], aa, wv[3]);
                }
            }
        }
    }

    #pragma unroll
    for (int r = 0; r < 8; r++) {
        int row = row_base + row0 + r;
        if (row >= NN) continue;
        unsigned long long dd = pack2(dinv_next[row]);
        union { float4 f; unsigned long long u[2]; } o0, o1;
        o0.u[0] = mul2(acc2[r][0], dd);
        o0.u[1] = mul2(acc2[r][1], dd);
        o1.u[0] = mul2(acc2[r][2], dd);
        o1.u[1] = mul2(acc2[r][3], dd);
        long base = (long)row * 32 + (col0 >> 2);
        reinterpret_cast<float4*>(g_out)[base]     = o0.f;
        reinterpret_cast<float4*>(g_out)[base + 1] = o1.f;
    }
}

__device__ __forceinline__ void load_a_tile(
    float (*As)[132], const float* __restrict__ A, int row_base, int tid)
{
    #pragma unroll
    for (int i = tid; i < 64 * 32; i += 128) {
        int r = i >> 5, c4 = i & 31;
        float4 v = make_float4(0.f, 0.f, 0.f, 0.f);
        if (row_base + r < NN)
            v = reinterpret_cast<const float4*>(A)[(long)(row_base + r) * 32 + c4];
        *reinterpret_cast<float4*>(&As[r][c4 * 4]) = v;
    }
}

// Standalone GEMM (layers 2-4): g = (A @ W) * dinv[row].
__global__ __launch_bounds__(128) void gemm_scale_kernel(
    const float* __restrict__ A, const float* __restrict__ W,
    const float* __restrict__ dinv, float* __restrict__ g)
{
    __shared__ float As[64][132];
    __shared__ float Ws[16][128];
    const int tid = threadIdx.x;
    const int row_base = blockIdx.x * 64;
    load_a_tile(As, A, row_base, tid);
    gemm_phase(As, Ws, W, dinv, g, row_base, tid);
}

// ---------------------------------------------------------------------------
// Combined launch: blocks [0, fill_blocks) do CSR fill (both edge sets),
// blocks [fill_blocks, ...) do layer-1 GEMM. The two halves are independent
// (fill needs scan_tiles; GEMM-1 needs only dinv1) and use complementary
// pipes (L2 atomics vs fma).
__global__ __launch_bounds__(128) void fill_gemm1_kernel(
    const int* __restrict__ ei1, int E1,
    int* __restrict__ cur1, int* __restrict__ col1,
    const int* __restrict__ ei2, int E2,
    int* __restrict__ cur2, int* __restrict__ col2,
    int fill_blocks,
    const float* __restrict__ A, const float* __restrict__ W,
    const float* __restrict__ dinv, float* __restrict__ g)
{
    if (blockIdx.x < fill_blocks) {
        int h1 = E1 >> 1, h2 = E2 >> 1;
        int i = blockIdx.x * blockDim.x + threadIdx.x;
        if (i < h1) {
            int2 s = reinterpret_cast<const int2*>(ei1)[i];
            int2 d = reinterpret_cast<const int2*>(ei1 + E1)[i];
            col1[atomicAdd(&cur1[d.x], 1)] = s.x;
            col1[atomicAdd(&cur1[d.y], 1)] = s.y;
        } else if (i < h1 + h2) {
            int2 s = reinterpret_cast<const int2*>(ei2)[i - h1];
            int2 d = reinterpret_cast<const int2*>(ei2 + E2)[i - h1];
            col2[atomicAdd(&cur2[d.x], 1)] = s.x;
            col2[atomicAdd(&cur2[d.y], 1)] = s.y;
        } else {
            int k = i - h1 - h2;
            if (k == 0 && (E1 & 1))
                col1[atomicAdd(&cur1[ei1[E1 + E1 - 1]], 1)] = ei1[E1 - 1];
            if (k == 1 && (E2 & 1))
                col2[atomicAdd(&cur2[ei2[E2 + E2 - 1]], 1)] = ei2[E2 - 1];
        }
        return;
    }
    __shared__ float As[64][132];
    __shared__ float Ws[16][128];
    const int tid = threadIdx.x;
    const int row_base = (blockIdx.x - fill_blocks) * 64;
    load_a_tile(As, A, row_base, tid);
    gemm_phase(As, Ws, W, dinv, g, row_base, tid);
}

// ---------------------------------------------------------------------------
// Gather + finalize: one warp per node, 4-way unrolled for MLP.
__global__ __launch_bounds__(256) void gather_finalize_kernel(
    const float4* __restrict__ g, const int* __restrict__ row_ptr,
    const int* __restrict__ col, const float* __restrict__ dinv,
    const float4* __restrict__ b, float4* __restrict__ out, int relu_mode)
{
    int warp = (blockIdx.x * blockDim.x + threadIdx.x) >> 5;
    int lane = threadIdx.x & 31;
    if (warp >= NN) return;

    long base = (long)warp * 32 + lane;
    float4 a0 = g[base];
    float4 a1 = make_float4(0.f, 0.f, 0.f, 0.f);
    float4 a2 = make_float4(0.f, 0.f, 0.f, 0.f);
    float4 a3 = make_float4(0.f, 0.f, 0.f, 0.f);

    int jb = __ldg(&row_ptr[warp]);
    int je = __ldg(&row_ptr[warp + 1]);
    int j = jb;
    for (; j + 3 < je; j += 4) {
        int s0 = __ldg(&col[j]);
        int s1 = __ldg(&col[j + 1]);
        int s2 = __ldg(&col[j + 2]);
        int s3 = __ldg(&col[j + 3]);
        float4 v0 = g[(long)s0 * 32 + lane];
        float4 v1 = g[(long)s1 * 32 + lane];
        float4 v2 = g[(long)s2 * 32 + lane];
        float4 v3 = g[(long)s3 * 32 + lane];
        a0.x += v0.x; a0.y += v0.y; a0.z += v0.z; a0.w += v0.w;
        a1.x += v1.x; a1.y += v1.y; a1.z += v1.z; a1.w += v1.w;
        a2.x += v2.x; a2.y += v2.y; a2.z += v2.z; a2.w += v2.w;
        a3.x += v3.x; a3.y += v3.y; a3.z += v3.z; a3.w += v3.w;
    }
    for (; j < je; j++) {
        int s = __ldg(&col[j]);
        float4 v = g[(long)s * 32 + lane];
        a0.x += v.x; a0.y += v.y; a0.z += v.z; a0.w += v.w;
    }
    a0.x += a1.x + a2.x + a3.x;
    a0.y += a1.y + a2.y + a3.y;
    a0.z += a1.z + a2.z + a3.z;
    a0.w += a1.w + a2.w + a3.w;

    float dv = dinv[warp];
    float4 bb = b[lane];
    float o[4] = { fmaf(a0.x, dv, bb.x), fmaf(a0.y, dv, bb.y),
                   fmaf(a0.z, dv, bb.z), fmaf(a0.w, dv, bb.w) };
    if (relu_mode) {
        #pragma unroll
        for (int k = 0; k < 4; k++) o[k] = fmaxf(o[k], 0.0f);
    } else {
        #pragma unroll
        for (int k = 0; k < 4; k++) o[k] = (o[k] > 0.0f) ? o[k] : expm1f(o[k]);
    }
    out[base] = make_float4(o[0], o[1], o[2], o[3]);
}

// ---------------------------------------------------------------------------
extern "C" void kernel_launch(void* const* d_in, const int* in_sizes, int n_in,
                              void* d_out, int out_size)
{
    const float* x  = (const float*)d_in[0];
    const float* W1 = (const float*)d_in[1]; const float* b1 = (const float*)d_in[2];
    const float* W2 = (const float*)d_in[3]; const float* b2 = (const float*)d_in[4];
    const float* W3 = (const float*)d_in[5]; const float* b3 = (const float*)d_in[6];
    const float* W4 = (const float*)d_in[7]; const float* b4 = (const float*)d_in[8];
    const int* ei1 = (const int*)d_in[9];
    const int* ei2 = (const int*)d_in[10];
    const int E1 = in_sizes[9] / 2;
    const int E2 = in_sizes[10] / 2;

    float *ga, *gb, *dinv1, *dinv2;
    int *cnt1, *cnt2, *rp1, *rp2, *cur1, *cur2, *col1, *col2, *p1, *p2;
    cudaGetSymbolAddress((void**)&ga,   g_ga);
    cudaGetSymbolAddress((void**)&gb,   g_gb);
    cudaGetSymbolAddress((void**)&dinv1, g_dinv1);
    cudaGetSymbolAddress((void**)&dinv2, g_dinv2);
    cudaGetSymbolAddress((void**)&cnt1, g_cnt1);
    cudaGetSymbolAddress((void**)&cnt2, g_cnt2);
    cudaGetSymbolAddress((void**)&rp1,  g_rowptr1);
    cudaGetSymbolAddress((void**)&rp2,  g_rowptr2);
    cudaGetSymbolAddress((void**)&cur1, g_cursor1);
    cudaGetSymbolAddress((void**)&cur2, g_cursor2);
    cudaGetSymbolAddress((void**)&col1, g_col1);
    cudaGetSymbolAddress((void**)&col2, g_col2);
    cudaGetSymbolAddress((void**)&p1,   g_part1);
    cudaGetSymbolAddress((void**)&p2,   g_part2);

    float* out_z = (float*)d_out;
    float* out_x = (float*)d_out + (long)NN * D;

    const int gemm_blocks = (NN + 63) / 64;
    const int gat_blocks  = (NN * 32 + 255) / 256;
    const int nedge2 = (E1 >> 1) + (E2 >> 1) + 2;
    const int fill_blocks = (nedge2 + 127) / 128;

    // ---- CSR build (counts start zeroed: zero-init + scan_tiles re-zeroes) ----
    count_both_kernel<<<(nedge2 + 255) / 256, 256>>>(ei1, E1, ei2, E2, cnt1, cnt2);
    partial_dinv_kernel<<<2 * NPART, 256>>>(cnt1, dinv1, p1, cnt2, dinv2, p2);
    scan_partials_kernel<<<2, 64>>>(p1, rp1, p2, rp2);
    scan_tiles_kernel<<<2 * NPART, 1024>>>(cnt1, rp1, cur1, p1, cnt2, rp2, cur2, p2);

    // fill (CSR cols) overlapped with layer-1 GEMM in one grid
    fill_gemm1_kernel<<<fill_blocks + gemm_blocks, 128>>>(
        ei1, E1, cur1, col1, ei2, E2, cur2, col2, fill_blocks,
        x, W1, dinv1, ga);

    // gather1 (elu) -> gb
    gather_finalize_kernel<<<gat_blocks, 256>>>(
        (const float4*)ga, rp1, col1, dinv1, (const float4*)b1, (float4*)gb, 0);
    // gemm2: gb -> ga (scaled by dinv2)
    gemm_scale_kernel<<<gemm_blocks, 128>>>(gb, W2, dinv2, ga);
    // gather2 (elu) -> out_z
    gather_finalize_kernel<<<gat_blocks, 256>>>(
        (const float4*)ga, rp2, col2, dinv2, (const float4*)b2, (float4*)out_z, 0);
    // gemm3: out_z -> ga (scaled by dinv1)
    gemm_scale_kernel<<<gemm_blocks, 128>>>(out_z, W3, dinv1, ga);
    // gather3 (elu) -> gb
    gather_finalize_kernel<<<gat_blocks, 256>>>(
        (const float4*)ga, rp1, col1, dinv1, (const float4*)b3, (float4*)gb, 0);
    // gemm4: gb -> ga (scaled by dinv2)
    gemm_scale_kernel<<<gemm_blocks, 128>>>(gb, W4, dinv2, ga);
    // gather4 (relu) -> out_x
    gather_finalize_kernel<<<gat_blocks, 256>>>(
        (const float4*)ga, rp2, col2, dinv2, (const float4*)b4, (float4*)out_x, 1);
}